// round 17
// baseline (speedup 1.0000x reference)
#include <cuda_runtime.h>
#include <cstdint>
#include <cstddef>

#define NMAX 20000
#define EMAX 320000

// ---------------- scratch (device globals; no allocation allowed) ----------------
__device__ int   g_count[NMAX];
__device__ int   g_offs[NMAX + 1];
__device__ int   g_cursor[NMAX];
__device__ int   g_esrc[EMAX];      // CSR payload: src node id per edge slot
__device__ float g_feat1[NMAX * 256];
__device__ float g_el1[NMAX * 4];
__device__ float g_er1[NMAX * 4];
__device__ float g_h2[NMAX * 256];
__device__ float g_feat2[NMAX * 64];
__device__ float g_el2[NMAX];
__device__ float g_er2[NMAX];

// ---------------- packed f32x2 helpers ------------------------------------------
__device__ __forceinline__ unsigned long long pack2(float x, float y) {
    unsigned long long r;
    asm("mov.b64 %0, {%1, %2};" : "=l"(r) : "f"(x), "f"(y));
    return r;
}
__device__ __forceinline__ float2 unpack2(unsigned long long v) {
    float2 r;
    asm("mov.b64 {%0, %1}, %2;" : "=f"(r.x), "=f"(r.y) : "l"(v));
    return r;
}
#define FMA2(d, a, b) asm("fma.rn.f32x2 %0, %1, %2, %0;" : "+l"(d) : "l"(a), "l"(b))

// ---------------- CSR build ------------------------------------------------------
__global__ void hist_k(const int* __restrict__ dst, int E) {
    int e = (blockIdx.x * blockDim.x + threadIdx.x) * 2;
    if (e + 1 < E) {
        int d0 = dst[e], d1 = dst[e + 1];
        atomicAdd(&g_count[d0], 1);
        atomicAdd(&g_count[d1], 1);
    } else if (e < E) {
        atomicAdd(&g_count[dst[e]], 1);
    }
}

__global__ void scan_k(int n) {
    __shared__ int part[1024];
    int tid = threadIdx.x;
    int per = (n + 1023) >> 10;
    int base = tid * per;
    int sum = 0;
    for (int i = 0; i < per; i++) {
        int idx = base + i;
        if (idx < n) sum += g_count[idx];
    }
    part[tid] = sum;
    __syncthreads();
    for (int off = 1; off < 1024; off <<= 1) {
        int t = (tid >= off) ? part[tid - off] : 0;
        __syncthreads();
        part[tid] += t;
        __syncthreads();
    }
    int run = part[tid] - sum;
    for (int i = 0; i < per; i++) {
        int idx = base + i;
        if (idx < n) {
            g_offs[idx] = run;
            g_cursor[idx] = run;
            run += g_count[idx];
        }
    }
    if (tid == 1023) g_offs[n] = part[1023];
}

__global__ void scatter_k(const int* __restrict__ dst, const int* __restrict__ src, int E) {
    int e = (blockIdx.x * blockDim.x + threadIdx.x) * 2;
    if (e + 1 < E) {
        int d0 = dst[e], d1 = dst[e + 1];
        int s0 = src[e], s1 = src[e + 1];
        int p0 = atomicAdd(&g_cursor[d0], 1);
        int p1 = atomicAdd(&g_cursor[d1], 1);
        g_esrc[p0] = s0;
        g_esrc[p1] = s1;
    } else if (e < E) {
        int p = atomicAdd(&g_cursor[dst[e]], 1);
        g_esrc[p] = src[e];
    }
}

// ---------------- GEMM (128x64 tile, 8x8 micro, dual-packed) + attn epilogue -----
// C[N,M] = A[N,K] @ B[K,M]. 128 threads (16x8), BK=16, register prefetch.
// Per-thread: 8 rows as 4 packed row-PAIRS (2 LDS.128) x 8 cols duplicated into
// f32x2 lanes (2 LDS.128 + 8 movs). 32 FMA2 per k-iter -> 2 B LDS per FMA2,
// 73% FMA2 instruction share. acc[c][p].lo = C[2p][c], .hi = C[2p+1][c].
// __launch_bounds__(128,4): 4 blocks/SM (occ 25%), fma-pipe bound by model.
// Each block covers ONE 64-col head; el/er reduced over aligned 8-lane groups.
__global__ __launch_bounds__(128, 4) void gemm_attn_k(const float* __restrict__ A,
                                                      const float* __restrict__ B,
                                                      float* __restrict__ C,
                                                      const float* __restrict__ al,
                                                      const float* __restrict__ ar,
                                                      float* __restrict__ el,
                                                      float* __restrict__ er,
                                                      int N, int K, int M) {
    __shared__ float As[16][128];   // transposed: As[k][row]; row pairs adjacent
    __shared__ float Bs[16][64];

    int tid = threadIdx.x;
    int tr = tid >> 3, tc = tid & 7;            // 16 x 8 threads
    int rowBase = blockIdx.y * 128, colBase = blockIdx.x * 64;

    unsigned long long acc[8][4];               // [col][rowpair]
#pragma unroll
    for (int c = 0; c < 8; c++)
#pragma unroll
        for (int p = 0; p < 4; p++) acc[c][p] = 0ull;

    float4 aReg[4], bReg[2];

    // prologue: chunk 0 -> registers
#pragma unroll
    for (int i = 0; i < 4; i++) {
        int f4 = tid + i * 128;
        int arow = f4 >> 2, acol = (f4 & 3) << 2;
        int grow = rowBase + arow;
        aReg[i] = (grow < N) ? *(const float4*)&A[(size_t)grow * K + acol]
                             : make_float4(0.f, 0.f, 0.f, 0.f);
    }
#pragma unroll
    for (int i = 0; i < 2; i++) {
        int f4 = tid + i * 128;
        int brow = f4 >> 4, bcol = (f4 & 15) << 2;
        bReg[i] = *(const float4*)&B[(size_t)brow * M + colBase + bcol];
    }

    int nChunks = K >> 4;
    for (int chunk = 0; chunk < nChunks; chunk++) {
        // stage registers -> smem
#pragma unroll
        for (int i = 0; i < 4; i++) {
            int f4 = tid + i * 128;
            int arow = f4 >> 2, acol = (f4 & 3) << 2;
            As[acol + 0][arow] = aReg[i].x;
            As[acol + 1][arow] = aReg[i].y;
            As[acol + 2][arow] = aReg[i].z;
            As[acol + 3][arow] = aReg[i].w;
        }
#pragma unroll
        for (int i = 0; i < 2; i++) {
            int f4 = tid + i * 128;
            int brow = f4 >> 4, bcol = (f4 & 15) << 2;
            *(float4*)&Bs[brow][bcol] = bReg[i];
        }
        __syncthreads();

        // prefetch next chunk
        if (chunk + 1 < nChunks) {
            int k0 = (chunk + 1) << 4;
#pragma unroll
            for (int i = 0; i < 4; i++) {
                int f4 = tid + i * 128;
                int arow = f4 >> 2, acol = (f4 & 3) << 2;
                int grow = rowBase + arow;
                aReg[i] = (grow < N) ? *(const float4*)&A[(size_t)grow * K + k0 + acol]
                                     : make_float4(0.f, 0.f, 0.f, 0.f);
            }
#pragma unroll
            for (int i = 0; i < 2; i++) {
                int f4 = tid + i * 128;
                int brow = f4 >> 4, bcol = (f4 & 15) << 2;
                bReg[i] = *(const float4*)&B[(size_t)(k0 + brow) * M + colBase + bcol];
            }
        }

#pragma unroll
        for (int k = 0; k < 16; k++) {
            // 8 rows = 4 row-pairs, packed straight from As (rows adjacent)
            const unsigned long long* ap = (const unsigned long long*)&As[k][tr << 3];
            unsigned long long a0 = ap[0], a1 = ap[1], a2 = ap[2], a3 = ap[3];
            float4 bv0 = *(const float4*)&Bs[k][tc << 3];
            float4 bv1 = *(const float4*)&Bs[k][(tc << 3) + 4];
            unsigned long long bd0 = pack2(bv0.x, bv0.x);
            unsigned long long bd1 = pack2(bv0.y, bv0.y);
            unsigned long long bd2 = pack2(bv0.z, bv0.z);
            unsigned long long bd3 = pack2(bv0.w, bv0.w);
            unsigned long long bd4 = pack2(bv1.x, bv1.x);
            unsigned long long bd5 = pack2(bv1.y, bv1.y);
            unsigned long long bd6 = pack2(bv1.z, bv1.z);
            unsigned long long bd7 = pack2(bv1.w, bv1.w);
            FMA2(acc[0][0], a0, bd0); FMA2(acc[0][1], a1, bd0);
            FMA2(acc[0][2], a2, bd0); FMA2(acc[0][3], a3, bd0);
            FMA2(acc[1][0], a0, bd1); FMA2(acc[1][1], a1, bd1);
            FMA2(acc[1][2], a2, bd1); FMA2(acc[1][3], a3, bd1);
            FMA2(acc[2][0], a0, bd2); FMA2(acc[2][1], a1, bd2);
            FMA2(acc[2][2], a2, bd2); FMA2(acc[2][3], a3, bd2);
            FMA2(acc[3][0], a0, bd3); FMA2(acc[3][1], a1, bd3);
            FMA2(acc[3][2], a2, bd3); FMA2(acc[3][3], a3, bd3);
            FMA2(acc[4][0], a0, bd4); FMA2(acc[4][1], a1, bd4);
            FMA2(acc[4][2], a2, bd4); FMA2(acc[4][3], a3, bd4);
            FMA2(acc[5][0], a0, bd5); FMA2(acc[5][1], a1, bd5);
            FMA2(acc[5][2], a2, bd5); FMA2(acc[5][3], a3, bd5);
            FMA2(acc[6][0], a0, bd6); FMA2(acc[6][1], a1, bd6);
            FMA2(acc[6][2], a2, bd6); FMA2(acc[6][3], a3, bd6);
            FMA2(acc[7][0], a0, bd7); FMA2(acc[7][1], a1, bd7);
            FMA2(acc[7][2], a2, bd7); FMA2(acc[7][3], a3, bd7);
        }
        __syncthreads();
    }

    // ---- epilogue: store C + fused attention scores ----
    int c0 = colBase + (tc << 3);
    int head = colBase >> 6;        // whole block is one head (TN=64)
    int H = M >> 6;
    float alv[8], arv[8];
#pragma unroll
    for (int j = 0; j < 8; j++) { alv[j] = al[c0 + j]; arv[j] = ar[c0 + j]; }

#pragma unroll
    for (int p = 0; p < 4; p++) {
        float2 q[8];
#pragma unroll
        for (int c = 0; c < 8; c++) q[c] = unpack2(acc[c][p]);
        int row0 = rowBase + (tr << 3) + (p << 1);
        int row1 = row0 + 1;
        if (row0 < N) {
            *(float4*)&C[(size_t)row0 * M + c0]     = make_float4(q[0].x, q[1].x, q[2].x, q[3].x);
            *(float4*)&C[(size_t)row0 * M + c0 + 4] = make_float4(q[4].x, q[5].x, q[6].x, q[7].x);
        }
        if (row1 < N) {
            *(float4*)&C[(size_t)row1 * M + c0]     = make_float4(q[0].y, q[1].y, q[2].y, q[3].y);
            *(float4*)&C[(size_t)row1 * M + c0 + 4] = make_float4(q[4].y, q[5].y, q[6].y, q[7].y);
        }

        float sl0 = 0.f, sr0 = 0.f, sl1 = 0.f, sr1 = 0.f;
#pragma unroll
        for (int c = 0; c < 8; c++) {
            sl0 += q[c].x * alv[c];
            sr0 += q[c].x * arv[c];
            sl1 += q[c].y * alv[c];
            sr1 += q[c].y * arv[c];
        }
#pragma unroll
        for (int o = 4; o; o >>= 1) {
            sl0 += __shfl_xor_sync(0xffffffffu, sl0, o);
            sr0 += __shfl_xor_sync(0xffffffffu, sr0, o);
            sl1 += __shfl_xor_sync(0xffffffffu, sl1, o);
            sr1 += __shfl_xor_sync(0xffffffffu, sr1, o);
        }
        if (tc == 0) {
            if (row0 < N) { el[row0 * H + head] = sl0; er[row0 * H + head] = sr0; }
            if (row1 < N) { el[row1 * H + head] = sl1; er[row1 * H + head] = sr1; }
        }
    }
}

// ---------------- fused per-node softmax + aggregation + bias(+ELU) -------------
template <int H, bool DO_ELU>
__global__ __launch_bounds__(256) void node_agg_k(const float* __restrict__ feat,
                           const float* __restrict__ el,
                           const float* __restrict__ er,
                           const float* __restrict__ bias, float* __restrict__ out,
                           int N) {
    constexpr int F = H * 64;
    constexpr int FP = F / 32;
    int w = (blockIdx.x * blockDim.x + threadIdx.x) >> 5;
    int lane = threadIdx.x & 31;
    if (w >= N) return;
    int beg = g_offs[w], end = g_offs[w + 1];

    float erh[H];
#pragma unroll
    for (int h = 0; h < H; h++) erh[h] = er[w * H + h];

    // ---- pass A: per-head max, lane-parallel over edges ----
    float mx[H];
#pragma unroll
    for (int h = 0; h < H; h++) mx[h] = -1e30f;
    for (int i = beg + lane; i < end; i += 32) {
        int s = g_esrc[i];
        if (H == 4) {
            float4 t = *(const float4*)&el[s * 4];
            float ev[4] = {t.x, t.y, t.z, t.w};
#pragma unroll
            for (int h = 0; h < 4; h++) {
                float v = ev[h] + erh[h];
                v = v > 0.f ? v : 0.2f * v;
                mx[h] = fmaxf(mx[h], v);
            }
        } else {
            float v = el[s] + erh[0];
            v = v > 0.f ? v : 0.2f * v;
            mx[0] = fmaxf(mx[0], v);
        }
    }
#pragma unroll
    for (int o = 16; o; o >>= 1)
#pragma unroll
        for (int h = 0; h < H; h++) mx[h] = fmaxf(mx[h], __shfl_xor_sync(0xffffffffu, mx[h], o));

    // ---- pass B: serial over edges, software-pipelined (prefetch s and el) ----
    float den[H];
#pragma unroll
    for (int h = 0; h < H; h++) den[h] = 0.f;
    float acc[FP];
#pragma unroll
    for (int j = 0; j < FP; j++) acc[j] = 0.f;
    int hsel = (lane * FP) >> 6;

    int sNext = (beg < end) ? g_esrc[beg] : 0;
    float4 tNext = make_float4(0.f, 0.f, 0.f, 0.f);
    float eNext = 0.f;
    if (beg < end) {
        if (H == 4) tNext = *(const float4*)&el[sNext * 4];
        else        eNext = el[sNext];
    }

    for (int i = beg; i < end; i++) {
        int s = sNext;
        float4 t = tNext;
        float es = eNext;
        int inext = i + 1;
        if (inext < end) {
            sNext = g_esrc[inext];
            if (H == 4) tNext = *(const float4*)&el[sNext * 4];
            else        eNext = el[sNext];
        }

        float ex[H];
        if (H == 4) {
            float ev[4] = {t.x, t.y, t.z, t.w};
#pragma unroll
            for (int h = 0; h < 4; h++) {
                float v = ev[h] + erh[h];
                v = v > 0.f ? v : 0.2f * v;
                ex[h] = __expf(v - mx[h]);
                den[h] += ex[h];
            }
        } else {
            float v = es + erh[0];
            v = v > 0.f ? v : 0.2f * v;
            ex[0] = __expf(v - mx[0]);
            den[0] += ex[0];
        }
        const float* fs = feat + (size_t)s * F + lane * FP;
        if (FP == 8) {
            float4 f0 = *(const float4*)fs;
            float4 f1 = *(const float4*)(fs + 4);
            float a = ex[hsel];
            acc[0] += f0.x * a; acc[1] += f0.y * a; acc[2] += f0.z * a; acc[3] += f0.w * a;
            acc[4] += f1.x * a; acc[5] += f1.y * a; acc[6] += f1.z * a; acc[7] += f1.w * a;
        } else {
            float2 f0 = *(const float2*)fs;
            float a = ex[0];
            acc[0] += f0.x * a;
            acc[1] += f0.y * a;
        }
    }

    float inv = (end > beg) ? 1.f / den[hsel] : 0.f;
    float* po = out + (size_t)w * F + lane * FP;
#pragma unroll
    for (int j = 0; j < FP; j++) {
        float r = acc[j] * inv + bias[lane * FP + j];
        if (DO_ELU) r = r > 0.f ? r : expm1f(r);
        po[j] = r;
    }
}

// ---------------- launch ---------------------------------------------------------
extern "C" void kernel_launch(void* const* d_in, const int* in_sizes, int n_in,
                              void* d_out, int out_size) {
    const float* X   = (const float*)d_in[0];
    const float* W1  = (const float*)d_in[1];
    const float* al1 = (const float*)d_in[2];
    const float* ar1 = (const float*)d_in[3];
    const float* b1  = (const float*)d_in[4];
    const float* W2  = (const float*)d_in[5];
    const float* al2 = (const float*)d_in[6];
    const float* ar2 = (const float*)d_in[7];
    const float* b2  = (const float*)d_in[8];
    const int*   src = (const int*)d_in[9];
    const int*   dst = (const int*)d_in[10];
    float* out = (float*)d_out;

    int N = in_sizes[0] / 256;
    int E = in_sizes[9];

    void *p_count, *p_feat1, *p_el1, *p_er1, *p_h2, *p_feat2, *p_el2, *p_er2;
    cudaGetSymbolAddress(&p_count, g_count);
    cudaGetSymbolAddress(&p_feat1, g_feat1);
    cudaGetSymbolAddress(&p_el1, g_el1);
    cudaGetSymbolAddress(&p_er1, g_er1);
    cudaGetSymbolAddress(&p_h2, g_h2);
    cudaGetSymbolAddress(&p_feat2, g_feat2);
    cudaGetSymbolAddress(&p_el2, g_el2);
    cudaGetSymbolAddress(&p_er2, g_er2);

    // CSR build
    cudaMemsetAsync(p_count, 0, (size_t)N * sizeof(int));
    int eThreads = (E + 1) / 2;
    hist_k<<<(eThreads + 255) / 256, 256>>>(dst, E);
    scan_k<<<1, 1024>>>(N);
    scatter_k<<<(eThreads + 255) / 256, 256>>>(dst, src, E);

    int rowBlocks = (N + 127) / 128;

    // Layer 1: GEMM (M=256) + fused attention scores
    gemm_attn_k<<<dim3(4, rowBlocks), 128>>>(X, W1, (float*)p_feat1, al1, ar1,
                                             (float*)p_el1, (float*)p_er1, N, 256, 256);
    node_agg_k<4, true><<<(N * 32 + 255) / 256, 256>>>(
        (const float*)p_feat1, (const float*)p_el1, (const float*)p_er1, b1,
        (float*)p_h2, N);

    // Layer 2: GEMM (M=64) + fused attention scores
    gemm_attn_k<<<dim3(1, rowBlocks), 128>>>((const float*)p_h2, W2, (float*)p_feat2,
                                             al2, ar2, (float*)p_el2, (float*)p_er2,
                                             N, 256, 64);
    node_agg_k<1, false><<<(N * 32 + 255) / 256, 256>>>(
        (const float*)p_feat2, (const float*)p_el2, (const float*)p_er2, b2, out, N);
}